// round 15
// baseline (speedup 1.0000x reference)
#include <cuda_runtime.h>
#include <math.h>
#include <stdint.h>

#define B_   2
#define T_   2048
#define D_   512
#define H_   8
#define HD_  64
#define QKV3 (3 * D_)   // 1536
#define NROW (B_ * T_)  // 4096

__device__ float    g_qkv[B_ * T_ * QKV3];
__device__ float    g_attn[B_ * T_ * D_];     // written tf32-rounded
__device__ uint32_t g_xt[NROW * D_];
__device__ uint32_t g_wqkvt[QKV3 * D_];
__device__ uint32_t g_woutt[D_ * D_];

__device__ __forceinline__ uint32_t f2tf32(float x) {
    uint32_t u;
    asm("cvt.rna.tf32.f32 %0, %1;" : "=r"(u) : "f"(x));
    return u;
}
__device__ __forceinline__ uint32_t smem_u32(const void* p) {
    uint32_t a;
    asm("{ .reg .u64 t; cvta.to.shared.u64 t, %1; cvt.u32.u64 %0, t; }"
        : "=r"(a) : "l"(p));
    return a;
}
__device__ __forceinline__ void mma8(float c[4], const uint32_t a[4], uint2 b) {
    asm volatile(
        "mma.sync.aligned.m16n8k8.row.col.f32.tf32.tf32.f32 "
        "{%0,%1,%2,%3}, {%4,%5,%6,%7}, {%8,%9}, {%0,%1,%2,%3};"
        : "+f"(c[0]), "+f"(c[1]), "+f"(c[2]), "+f"(c[3])
        : "r"(a[0]), "r"(a[1]), "r"(a[2]), "r"(a[3]), "r"(b.x), "r"(b.y));
}
__device__ __forceinline__ void ldsm4(uint32_t r[4], uint32_t addr) {
    asm volatile("ldmatrix.sync.aligned.m8n8.x4.shared.b16 {%0,%1,%2,%3}, [%4];"
                 : "=r"(r[0]), "=r"(r[1]), "=r"(r[2]), "=r"(r[3]) : "r"(addr));
}
__device__ __forceinline__ void cpa16(uint32_t dst, const void* src) {
    asm volatile("cp.async.cg.shared.global [%0], [%1], 16;" :: "r"(dst), "l"(src));
}
#define CP_COMMIT() asm volatile("cp.async.commit_group;" ::: "memory")
#define CP_WAIT(n)  asm volatile("cp.async.wait_group %0;" :: "n"(n) : "memory")

// ---------------------------------------------------------------------------
// Fused prepass: x / w_qkv / w_out -> tf32 bits, one launch
// ---------------------------------------------------------------------------
#define N4X (NROW * D_ / 4)
#define N4Q (QKV3 * D_ / 4)
#define N4O (D_ * D_ / 4)

__global__ void cvt_all_kernel(const float* __restrict__ x,
                               const float* __restrict__ wq,
                               const float* __restrict__ wo)
{
    int i = blockIdx.x * blockDim.x + threadIdx.x;
    int stride = gridDim.x * blockDim.x;
    const int ntot = N4X + N4Q + N4O;
    for (; i < ntot; i += stride) {
        const float4* src;
        uint4* dst;
        if (i < N4X)            { src = (const float4*)x  + i;
                                  dst = (uint4*)g_xt + i; }
        else if (i < N4X + N4Q) { src = (const float4*)wq + (i - N4X);
                                  dst = (uint4*)g_wqkvt + (i - N4X); }
        else                    { src = (const float4*)wo + (i - N4X - N4Q);
                                  dst = (uint4*)g_woutt + (i - N4X - N4Q); }
        float4 v = *src;
        *dst = make_uint4(f2tf32(v.x), f2tf32(v.y), f2tf32(v.z), f2tf32(v.w));
    }
}

// ---------------------------------------------------------------------------
// TF32 GEMM v7: 3-stage cp.async ring, 60KB smem -> 2 blocks/SM.
// Block 128x128, BK=16, 256 thr, 8 warps (2x4) of 64x32, ldmatrix frags.
// ---------------------------------------------------------------------------
#define RB   80
#define TILE_B (128 * RB)          // 10240 B per matrix per stage
#define NSTG 3
#define G7_SMEM (NSTG * 2 * TILE_B)   // 61440 B

__global__ __launch_bounds__(256, 2)
void gemm_tf32_v7(const uint32_t* __restrict__ A, const uint32_t* __restrict__ W,
                  const float* __restrict__ bias, float* __restrict__ C,
                  int N, int M, int K)
{
    extern __shared__ char sm7[];
    const uint32_t Abase = smem_u32(sm7);
    const uint32_t Wbase = Abase + NSTG * TILE_B;

    const int tid  = threadIdx.x;
    const int warp = tid >> 5;
    const int lane = tid & 31;
    const int g    = lane >> 2;
    const int t4   = lane & 3;

    const int n0 = blockIdx.y * 128;
    const int m0 = blockIdx.x * 128;
    const int r0 = (warp >> 2) * 64;
    const int c0 = (warp & 3) * 32;

    const int lmrow = (lane & 7) + (((lane >> 3) & 1) << 3);
    const int lmc   = (lane >> 4) * 16;

    const int srow0 = tid >> 2, sc0 = (tid & 3) * 4;
    const int srow1 = srow0 + 64;
    const uint32_t* Ag0 = A + (size_t)(n0 + srow0) * K + sc0;
    const uint32_t* Ag1 = A + (size_t)(n0 + srow1) * K + sc0;
    const uint32_t* Wg0 = W + (size_t)(m0 + srow0) * K + sc0;
    const uint32_t* Wg1 = W + (size_t)(m0 + srow1) * K + sc0;
    const uint32_t sA0 = srow0 * RB + sc0 * 4;
    const uint32_t sA1 = srow1 * RB + sc0 * 4;

    float c[4][4][4];
#pragma unroll
    for (int mi = 0; mi < 4; mi++)
#pragma unroll
        for (int ni = 0; ni < 4; ni++)
#pragma unroll
            for (int q = 0; q < 4; q++) c[mi][ni][q] = 0.f;

#define STAGE7(buf, koff)                                        \
    {                                                            \
        cpa16(Abase + (buf) * TILE_B + sA0, Ag0 + (koff));       \
        cpa16(Abase + (buf) * TILE_B + sA1, Ag1 + (koff));       \
        cpa16(Wbase + (buf) * TILE_B + sA0, Wg0 + (koff));       \
        cpa16(Wbase + (buf) * TILE_B + sA1, Wg1 + (koff));       \
    }

    const int NT = K / 16;
    STAGE7(0, 0);  CP_COMMIT();
    STAGE7(1, 16); CP_COMMIT();

    int bufc = 0;
    for (int it = 0; it < NT; it++) {
        CP_WAIT(1);
        __syncthreads();
        // prefetch stage it+2 into buffer (bufc+2)%3 (= buffer of it-1; all
        // warps finished its compute having passed the barrier above)
        int pf = bufc + 2; if (pf >= NSTG) pf -= NSTG;
        if (it + 2 < NT) { STAGE7(pf, (it + 2) * 16); }
        CP_COMMIT();

        const uint32_t ab = Abase + bufc * TILE_B + (r0 + lmrow) * RB + lmc;
        const uint32_t wb = Wbase + bufc * TILE_B + (c0 + lmrow) * RB + lmc;
#pragma unroll
        for (int kh = 0; kh < 2; kh++) {
            uint32_t bfr[2][4];
            ldsm4(bfr[0], wb + kh * 32);
            ldsm4(bfr[1], wb + 16 * RB + kh * 32);
#pragma unroll
            for (int mi = 0; mi < 4; mi++) {
                uint32_t afr[4];
                ldsm4(afr, ab + mi * 16 * RB + kh * 32);
                mma8(c[mi][0], afr, make_uint2(bfr[0][0], bfr[0][2]));
                mma8(c[mi][1], afr, make_uint2(bfr[0][1], bfr[0][3]));
                mma8(c[mi][2], afr, make_uint2(bfr[1][0], bfr[1][2]));
                mma8(c[mi][3], afr, make_uint2(bfr[1][1], bfr[1][3]));
            }
        }
        bufc++; if (bufc >= NSTG) bufc = 0;
    }
    __syncthreads();

#pragma unroll
    for (int mi = 0; mi < 4; mi++) {
        int row_a = n0 + r0 + mi * 16 + g;
        int row_b = row_a + 8;
#pragma unroll
        for (int ni = 0; ni < 4; ni++) {
            int col = m0 + c0 + ni * 8 + 2 * t4;
            float bx = bias[col], by = bias[col + 1];
            *(float2*)(C + (size_t)row_a * M + col) =
                make_float2(c[mi][ni][0] + bx, c[mi][ni][1] + by);
            *(float2*)(C + (size_t)row_b * M + col) =
                make_float2(c[mi][ni][2] + bx, c[mi][ni][3] + by);
        }
    }
#undef STAGE7
}

// ---------------------------------------------------------------------------
// MMA residue-class flash attention (round-10 proven; tf32-rounded epilogue).
// ---------------------------------------------------------------------------
#define KST 36
#define PST 76
#define ATTN_SMEM (64*KST*8 + 64*KST*8 + 64*PST*4 + 128*4 + 128*4)

__global__ __launch_bounds__(256, 2)
void attn_mma(const int* __restrict__ periods)
{
    extern __shared__ char smc[];
    uint2* Ks2 = (uint2*)smc;
    uint2* Vt2 = Ks2 + 64 * KST;
    float* Ps  = (float*)(Vt2 + 64 * KST);
    float* Pmx = Ps + 64 * PST;
    float* Psm = Pmx + 128;

    const int bh = blockIdx.y;
    const int b  = bh >> 3;
    const int h  = bh & 7;
    int p = periods[bh];
    if (p < 1) p = 1;

    const int x    = blockIdx.x;
    const int r    = x % p;
    const int tile = x / p;
    const int c0   = tile * 64;
    const int L    = (T_ - 1 - r) / p + 1;
    if (c0 >= L) return;
    const int cmax = min(c0 + 63, L - 1);
    const int kmax = cmax;

    const int tid  = threadIdx.x;
    const int warp = tid >> 5;
    const int lane = tid & 31;
    const int g    = lane >> 2;
    const int t4   = lane & 3;
    const int mt   = warp >> 1;
    const int nh   = warp & 1;

    const float* base = g_qkv + (size_t)b * T_ * QKV3;
    const float NEG = __int_as_float(0xff800000);

    for (int i = tid; i < 64 * KST; i += 256) {
        Ks2[i] = make_uint2(0u, 0u);
        Vt2[i] = make_uint2(0u, 0u);
    }
    for (int u = tid; u < 64 * 16; u += 256) {
        int row = u >> 4, q4 = (u & 15) * 4;
        float4 v = make_float4(0.f, 0.f, 0.f, 0.f);
        int cq = c0 + row;
        if (cq <= cmax) {
            int iq = r + cq * p;
            v = *(const float4*)(base + (size_t)iq * QKV3 + h * HD_ + q4);
            v.x *= 0.125f; v.y *= 0.125f; v.z *= 0.125f; v.w *= 0.125f;
        }
        *(float4*)(Ps + row * PST + q4) = v;
    }
    __syncthreads();

    uint32_t qa[8][4];
    {
        const float* q0 = Ps + (mt * 16 + g) * PST;
        const float* q1 = q0 + 8 * PST;
#pragma unroll
        for (int s = 0; s < 8; s++) {
            qa[s][0] = f2tf32(q0[8 * s + t4]);
            qa[s][1] = f2tf32(q1[8 * s + t4]);
            qa[s][2] = f2tf32(q0[8 * s + 4 + t4]);
            qa[s][3] = f2tf32(q1[8 * s + 4 + t4]);
        }
    }

    float m0 = -1e30f, m1 = -1e30f, l0 = 0.f, l1 = 0.f;
    float o[4][4];
#pragma unroll
    for (int ns = 0; ns < 4; ns++)
#pragma unroll
        for (int j = 0; j < 4; j++) o[ns][j] = 0.f;

    const int cq0 = c0 + mt * 16 + g;
    const int cq1 = cq0 + 8;
    const int lim0 = (cq0 <= cmax) ? cq0 : -1;
    const int lim1 = (cq1 <= cmax) ? cq1 : -1;
    const int row0 = mt * 16 + g;
    const int row1 = row0 + 8;

    const int niter = kmax / 64 + 1;
    for (int t = 0; t < niter; t++) {
        __syncthreads();
#pragma unroll
        for (int uu = 0; uu < 2; uu++) {
            int u = tid + 256 * uu;
            int key = u >> 3, s = u & 7;
            int ck = 64 * t + key;
            if (ck <= kmax) {
                int ik = r + ck * p;
                const float* kp_ = base + (size_t)ik * QKV3 + D_ + h * HD_ + 8 * s;
                float4 f0 = *(const float4*)kp_;
                float4 f1 = *(const float4*)(kp_ + 4);
                uint2* dst = Ks2 + key * KST + 4 * s;
                dst[0] = make_uint2(f2tf32(f0.x), f2tf32(f1.x));
                dst[1] = make_uint2(f2tf32(f0.y), f2tf32(f1.y));
                dst[2] = make_uint2(f2tf32(f0.z), f2tf32(f1.z));
                dst[3] = make_uint2(f2tf32(f0.w), f2tf32(f1.w));
                float4 v0 = *(const float4*)(kp_ + D_);
                float4 v1 = *(const float4*)(kp_ + D_ + 4);
                uint32_t* vt = (uint32_t*)Vt2;
                int wb = 2 * ((key >> 3) * 4 + (key & 3)) + ((key >> 2) & 1);
                vt[(8 * s + 0) * 2 * KST + wb] = f2tf32(v0.x);
                vt[(8 * s + 1) * 2 * KST + wb] = f2tf32(v0.y);
                vt[(8 * s + 2) * 2 * KST + wb] = f2tf32(v0.z);
                vt[(8 * s + 3) * 2 * KST + wb] = f2tf32(v0.w);
                vt[(8 * s + 4) * 2 * KST + wb] = f2tf32(v1.x);
                vt[(8 * s + 5) * 2 * KST + wb] = f2tf32(v1.y);
                vt[(8 * s + 6) * 2 * KST + wb] = f2tf32(v1.z);
                vt[(8 * s + 7) * 2 * KST + wb] = f2tf32(v1.w);
            }
        }
        __syncthreads();

        float sf[4][4];
#pragma unroll
        for (int ns = 0; ns < 4; ns++) {
#pragma unroll
            for (int j = 0; j < 4; j++) sf[ns][j] = 0.f;
            const uint2* kb = Ks2 + (nh * 32 + ns * 8 + g) * KST;
#pragma unroll
            for (int s = 0; s < 8; s++)
                mma8(sf[ns], qa[s], kb[4 * s + t4]);
        }
        float rx0 = NEG, rx1 = NEG;
#pragma unroll
        for (int ns = 0; ns < 4; ns++) {
            int ck = 64 * t + nh * 32 + ns * 8 + 2 * t4;
            sf[ns][0] = (ck     <= lim0) ? sf[ns][0] : NEG;
            sf[ns][1] = (ck + 1 <= lim0) ? sf[ns][1] : NEG;
            sf[ns][2] = (ck     <= lim1) ? sf[ns][2] : NEG;
            sf[ns][3] = (ck + 1 <= lim1) ? sf[ns][3] : NEG;
            rx0 = fmaxf(rx0, fmaxf(sf[ns][0], sf[ns][1]));
            rx1 = fmaxf(rx1, fmaxf(sf[ns][2], sf[ns][3]));
        }
        rx0 = fmaxf(rx0, __shfl_xor_sync(0xffffffffu, rx0, 1));
        rx0 = fmaxf(rx0, __shfl_xor_sync(0xffffffffu, rx0, 2));
        rx1 = fmaxf(rx1, __shfl_xor_sync(0xffffffffu, rx1, 1));
        rx1 = fmaxf(rx1, __shfl_xor_sync(0xffffffffu, rx1, 2));
        if (t4 == 0) {
            Pmx[nh * 64 + row0] = rx0;
            Pmx[nh * 64 + row1] = rx1;
        }
        __syncthreads();
        float nm0 = fmaxf(m0, fmaxf(Pmx[row0], Pmx[64 + row0]));
        float nm1 = fmaxf(m1, fmaxf(Pmx[row1], Pmx[64 + row1]));
        float co0 = __expf(m0 - nm0);
        float co1 = __expf(m1 - nm1);
        m0 = nm0; m1 = nm1;

        float ps0 = 0.f, ps1 = 0.f;
#pragma unroll
        for (int ns = 0; ns < 4; ns++) {
            int col = nh * 32 + ns * 8 + 2 * t4;
            float p00 = __uint_as_float(f2tf32(__expf(sf[ns][0] - nm0)));
            float p01 = __uint_as_float(f2tf32(__expf(sf[ns][1] - nm0)));
            float p10 = __uint_as_float(f2tf32(__expf(sf[ns][2] - nm1)));
            float p11 = __uint_as_float(f2tf32(__expf(sf[ns][3] - nm1)));
            ps0 += p00 + p01;
            ps1 += p10 + p11;
            *(float2*)(Ps + row0 * PST + col) = make_float2(p00, p01);
            *(float2*)(Ps + row1 * PST + col) = make_float2(p10, p11);
        }
        ps0 += __shfl_xor_sync(0xffffffffu, ps0, 1);
        ps0 += __shfl_xor_sync(0xffffffffu, ps0, 2);
        ps1 += __shfl_xor_sync(0xffffffffu, ps1, 1);
        ps1 += __shfl_xor_sync(0xffffffffu, ps1, 2);
        if (t4 == 0) {
            Psm[nh * 64 + row0] = ps0;
            Psm[nh * 64 + row1] = ps1;
        }
        __syncthreads();
        l0 = l0 * co0 + Psm[row0] + Psm[64 + row0];
        l1 = l1 * co1 + Psm[row1] + Psm[64 + row1];

#pragma unroll
        for (int ns = 0; ns < 4; ns++) {
            o[ns][0] *= co0; o[ns][1] *= co0;
            o[ns][2] *= co1; o[ns][3] *= co1;
        }
        const float* pr0 = Ps + row0 * PST;
        const float* pr1 = Ps + row1 * PST;
#pragma unroll
        for (int s = 0; s < 8; s++) {
            uint32_t pa[4];
            pa[0] = __float_as_uint(pr0[8 * s + t4]);
            pa[1] = __float_as_uint(pr1[8 * s + t4]);
            pa[2] = __float_as_uint(pr0[8 * s + 4 + t4]);
            pa[3] = __float_as_uint(pr1[8 * s + 4 + t4]);
#pragma unroll
            for (int ns = 0; ns < 4; ns++) {
                uint2 vb = Vt2[(nh * 32 + ns * 8 + g) * KST + 4 * s + t4];
                mma8(o[ns], pa, vb);
            }
        }
    }

    float inv0 = 1.f / l0;
    float inv1 = 1.f / l1;
    if (cq0 <= cmax) {
        float* orow = g_attn + (size_t)(b * T_ + (r + cq0 * p)) * D_ + h * HD_;
#pragma unroll
        for (int ns = 0; ns < 4; ns++) {
            int col = nh * 32 + ns * 8 + 2 * t4;
            *(uint2*)(orow + col) = make_uint2(f2tf32(o[ns][0] * inv0),
                                               f2tf32(o[ns][1] * inv0));
        }
    }
    if (cq1 <= cmax) {
        float* orow = g_attn + (size_t)(b * T_ + (r + cq1 * p)) * D_ + h * HD_;
#pragma unroll
        for (int ns = 0; ns < 4; ns++) {
            int col = nh * 32 + ns * 8 + 2 * t4;
            *(uint2*)(orow + col) = make_uint2(f2tf32(o[ns][2] * inv1),
                                               f2tf32(o[ns][3] * inv1));
        }
    }
}

// ---------------------------------------------------------------------------
extern "C" void kernel_launch(void* const* d_in, const int* in_sizes, int n_in,
                              void* d_out, int out_size)
{
    const float* x      = (const float*)d_in[0];
    const int*   periods= (const int*)  d_in[1];
    const float* w_qkv  = (const float*)d_in[2];
    const float* b_qkv  = (const float*)d_in[3];
    const float* w_out  = (const float*)d_in[4];
    const float* b_out  = (const float*)d_in[5];
    float*       out    = (float*)d_out;

    float *qkv_ptr, *attn_ptr;
    uint32_t *xt, *wqt, *wot;
    cudaGetSymbolAddress((void**)&qkv_ptr, g_qkv);
    cudaGetSymbolAddress((void**)&attn_ptr, g_attn);
    cudaGetSymbolAddress((void**)&xt,  g_xt);
    cudaGetSymbolAddress((void**)&wqt, g_wqkvt);
    cudaGetSymbolAddress((void**)&wot, g_woutt);

    static bool attr_set = false;
    if (!attr_set) {
        cudaFuncSetAttribute(attn_mma,
                             cudaFuncAttributeMaxDynamicSharedMemorySize,
                             ATTN_SMEM);
        cudaFuncSetAttribute(gemm_tf32_v7,
                             cudaFuncAttributeMaxDynamicSharedMemorySize,
                             G7_SMEM);
        attr_set = true;
    }

    // 0) fused prepass
    cvt_all_kernel<<<592, 256>>>(x, w_qkv, w_out);

    {   // 1) QKV projection
        dim3 grid(QKV3 / 128, NROW / 128);
        gemm_tf32_v7<<<grid, 256, G7_SMEM>>>(xt, wqt, b_qkv, qkv_ptr,
                                             NROW, QKV3, D_);
    }
    {   // 2) periodic-causal attention
        dim3 grid(64, B_ * H_);
        attn_mma<<<grid, 256, ATTN_SMEM>>>(periods);
    }
    {   // 3) output projection (g_attn already tf32-rounded)
        dim3 grid(D_ / 128, NROW / 128);
        gemm_tf32_v7<<<grid, 256, G7_SMEM>>>((const uint32_t*)attn_ptr, wot,
                                             b_out, out, NROW, D_, D_);
    }
}